// round 2
// baseline (speedup 1.0000x reference)
#include <cuda_runtime.h>
#include <cuda_fp16.h>
#include <cstdint>

// ---------------- problem dims ----------------
#define MTOK 8192   // B*S
#define HDIM 2048   // H
#define IDIM 8192   // I
// group_size G = 128 (hardcoded)

// ---------------- device scratch ----------------
__device__ __half g_x16[(size_t)MTOK * HDIM];   //  32 MB
__device__ __half g_wgq[(size_t)IDIM * HDIM];   //  32 MB
__device__ __half g_wuq[(size_t)IDIM * HDIM];   //  32 MB
__device__ __half g_wdq[(size_t)HDIM * IDIM];   //  32 MB
__device__ __half g_h16[(size_t)MTOK * IDIM];   // 128 MB

// ---------------- helpers ----------------
__device__ __forceinline__ uint32_t smem_u32(const void* p) {
    uint32_t a;
    asm("{ .reg .u64 t; cvta.to.shared.u64 t, %1; cvt.u32.u64 %0, t; }"
        : "=r"(a) : "l"(p));
    return a;
}

__device__ __forceinline__ void cp_async16(uint32_t dst, const void* src) {
    asm volatile("cp.async.cg.shared.global [%0], [%1], 16;"
                 :: "r"(dst), "l"(src) : "memory");
}
__device__ __forceinline__ void cp_commit() {
    asm volatile("cp.async.commit_group;" ::: "memory");
}
template <int N>
__device__ __forceinline__ void cp_wait() {
    asm volatile("cp.async.wait_group %0;" :: "n"(N) : "memory");
}

__device__ __forceinline__ void ldsm4(uint32_t& r0, uint32_t& r1, uint32_t& r2,
                                      uint32_t& r3, uint32_t addr) {
    asm volatile("ldmatrix.sync.aligned.m8n8.x4.shared.b16 {%0,%1,%2,%3}, [%4];"
                 : "=r"(r0), "=r"(r1), "=r"(r2), "=r"(r3) : "r"(addr));
}

__device__ __forceinline__ void mma16816(float& c0, float& c1, float& c2, float& c3,
                                         uint32_t a0, uint32_t a1, uint32_t a2, uint32_t a3,
                                         uint32_t b0, uint32_t b1) {
    asm volatile(
        "mma.sync.aligned.m16n8k16.row.col.f32.f16.f16.f32 "
        "{%0,%1,%2,%3}, {%4,%5,%6,%7}, {%8,%9}, {%0,%1,%2,%3};"
        : "+f"(c0), "+f"(c1), "+f"(c2), "+f"(c3)
        : "r"(a0), "r"(a1), "r"(a2), "r"(a3), "r"(b0), "r"(b1));
}

// ---------------- prep kernels ----------------
__global__ void __launch_bounds__(256) quant_kernel(const float* __restrict__ w,
                                                    __half* __restrict__ q, int ngroups) {
    int g = blockIdx.x * 8 + (threadIdx.x >> 5);
    if (g >= ngroups) return;
    int lane = threadIdx.x & 31;
    const float4 v = reinterpret_cast<const float4*>(w + (size_t)g * 128)[lane];
    float s = fabsf(v.x) + fabsf(v.y) + fabsf(v.z) + fabsf(v.w);
    #pragma unroll
    for (int o = 16; o; o >>= 1) s += __shfl_xor_sync(0xffffffffu, s, o);
    s *= (1.0f / 128.0f);
    float f[4] = {v.x, v.y, v.z, v.w};
    alignas(8) __half r[4];
    #pragma unroll
    for (int i = 0; i < 4; i++) {
        float sv = (f[i] > 0.f) ? s : ((f[i] < 0.f) ? -s : 0.f);
        r[i] = __float2half_rn(sv);
    }
    *reinterpret_cast<uint2*>(q + (size_t)g * 128 + lane * 4) =
        *reinterpret_cast<const uint2*>(r);
}

__global__ void __launch_bounds__(256) cvt_kernel(const float* __restrict__ x,
                                                  __half* __restrict__ y, int n4) {
    int i = blockIdx.x * 256 + threadIdx.x;
    if (i >= n4) return;
    float4 v = reinterpret_cast<const float4*>(x)[i];
    alignas(8) __half r[4] = {__float2half_rn(v.x), __float2half_rn(v.y),
                              __float2half_rn(v.z), __float2half_rn(v.w)};
    reinterpret_cast<uint2*>(y)[i] = *reinterpret_cast<const uint2*>(r);
}

// ---------------- GEMM building blocks ----------------
// SMEM tile: 128 rows x 64 halves (128B/row), 8x 16B chunks per row,
// chunk swizzle: phys = chunk ^ (row & 7).
// load one 128x64 block with cp.async (256 threads, 4 chunks each)
template <int LDK>
__device__ __forceinline__ void load_block(uint32_t sdst, const __half* __restrict__ g,
                                           int row0, int k0, int tid) {
    #pragma unroll
    for (int i = 0; i < 4; i++) {
        int lin = tid + i * 256;
        int r = lin >> 3, c = lin & 7;
        const __half* src = g + (size_t)(row0 + r) * LDK + k0 + c * 8;
        uint32_t dst = sdst + r * 128 + ((c ^ (r & 7)) << 4);
        cp_async16(dst, src);
    }
}

// fragment address within a tile: logical row r, k-step kk (0..3), lane
__device__ __forceinline__ uint32_t frag_addr(uint32_t tile, int rbase, int kk, int lane) {
    int r = rbase + (lane & 15);
    int chunk = kk * 2 + (lane >> 4);
    return tile + r * 128 + ((chunk ^ (r & 7)) << 4);
}

// ---------------- GEMM 1: fused gate/up + SwiGLU ----------------
// D_g[m,i] = sum_h x[m,h] wg[i,h]; h16 = silu(Dg)*Du
static constexpr int G1_STAGES = 3;
static constexpr int G1_KITER = HDIM / 64;           // 32
static constexpr uint32_t G1_STAGE_B = 3 * 16384;    // A + Bg + Bu
static constexpr uint32_t G1_SMEM = G1_STAGES * G1_STAGE_B;  // 147456

__global__ void __launch_bounds__(256, 1)
gemm1_kernel(const __half* __restrict__ A, const __half* __restrict__ Bg,
             const __half* __restrict__ Bu, __half* __restrict__ hout) {
    extern __shared__ char smem_raw[];
    const uint32_t sb = smem_u32(smem_raw);
    const int tid = threadIdx.x, wid = tid >> 5, lane = tid & 31;
    const int wm = wid >> 2, wn = wid & 3;           // warp tile 64(m) x 32(n)

    // supertile raster
    constexpr int TILES_N = IDIM / 128;              // 64
    constexpr int GM = 8;
    int bid = blockIdx.x;
    int width = GM * TILES_N;
    int grp = bid / width, rem = bid - grp * width;
    int m0 = (grp * GM + (rem % GM)) * 128;
    int n0 = (rem / GM) * 128;

    float accG[4][4][4];
    float accU[4][4][4];
    #pragma unroll
    for (int i = 0; i < 4; i++)
        #pragma unroll
        for (int j = 0; j < 4; j++)
            #pragma unroll
            for (int e = 0; e < 4; e++) { accG[i][j][e] = 0.f; accU[i][j][e] = 0.f; }

    // prologue: fill STAGES-1 stages
    #pragma unroll
    for (int s = 0; s < G1_STAGES - 1; s++) {
        uint32_t st = sb + s * G1_STAGE_B;
        load_block<HDIM>(st,          A,  m0, s * 64, tid);
        load_block<HDIM>(st + 16384,  Bg, n0, s * 64, tid);
        load_block<HDIM>(st + 32768,  Bu, n0, s * 64, tid);
        cp_commit();
    }

    for (int k = 0; k < G1_KITER; k++) {
        cp_wait<G1_STAGES - 2>();
        __syncthreads();
        int cur = k % G1_STAGES;
        // prefetch
        int pf = k + G1_STAGES - 1;
        if (pf < G1_KITER) {
            uint32_t st = sb + (pf % G1_STAGES) * G1_STAGE_B;
            load_block<HDIM>(st,         A,  m0, pf * 64, tid);
            load_block<HDIM>(st + 16384, Bg, n0, pf * 64, tid);
            load_block<HDIM>(st + 32768, Bu, n0, pf * 64, tid);
        }
        cp_commit();

        uint32_t tA  = sb + cur * G1_STAGE_B;
        uint32_t tBg = tA + 16384;
        uint32_t tBu = tA + 32768;
        #pragma unroll
        for (int kk = 0; kk < 4; kk++) {
            uint32_t a[4][4];
            #pragma unroll
            for (int mf = 0; mf < 4; mf++)
                ldsm4(a[mf][0], a[mf][1], a[mf][2], a[mf][3],
                      frag_addr(tA, wm * 64 + mf * 16, kk, lane));
            // gate
            {
                uint32_t b[4][2];
                #pragma unroll
                for (int p = 0; p < 2; p++) {
                    uint32_t r0, r1, r2, r3;
                    ldsm4(r0, r1, r2, r3, frag_addr(tBg, wn * 32 + p * 16, kk, lane));
                    b[p*2][0] = r0; b[p*2][1] = r2; b[p*2+1][0] = r1; b[p*2+1][1] = r3;
                }
                #pragma unroll
                for (int mf = 0; mf < 4; mf++)
                    #pragma unroll
                    for (int nf = 0; nf < 4; nf++)
                        mma16816(accG[mf][nf][0], accG[mf][nf][1], accG[mf][nf][2], accG[mf][nf][3],
                                 a[mf][0], a[mf][1], a[mf][2], a[mf][3], b[nf][0], b[nf][1]);
            }
            // up
            {
                uint32_t b[4][2];
                #pragma unroll
                for (int p = 0; p < 2; p++) {
                    uint32_t r0, r1, r2, r3;
                    ldsm4(r0, r1, r2, r3, frag_addr(tBu, wn * 32 + p * 16, kk, lane));
                    b[p*2][0] = r0; b[p*2][1] = r2; b[p*2+1][0] = r1; b[p*2+1][1] = r3;
                }
                #pragma unroll
                for (int mf = 0; mf < 4; mf++)
                    #pragma unroll
                    for (int nf = 0; nf < 4; nf++)
                        mma16816(accU[mf][nf][0], accU[mf][nf][1], accU[mf][nf][2], accU[mf][nf][3],
                                 a[mf][0], a[mf][1], a[mf][2], a[mf][3], b[nf][0], b[nf][1]);
            }
        }
        __syncthreads();
    }

    // epilogue: h = silu(g)*u, fp16 out
    #pragma unroll
    for (int mf = 0; mf < 4; mf++) {
        #pragma unroll
        for (int nf = 0; nf < 4; nf++) {
            int r = m0 + wm * 64 + mf * 16 + (lane >> 2);
            int c = n0 + wn * 32 + nf * 8 + ((lane & 3) << 1);
            float g0 = accG[mf][nf][0], g1 = accG[mf][nf][1];
            float u0 = accU[mf][nf][0], u1 = accU[mf][nf][1];
            float h0 = u0 * (g0 / (1.0f + __expf(-g0)));
            float h1 = u1 * (g1 / (1.0f + __expf(-g1)));
            *reinterpret_cast<__half2*>(hout + (size_t)r * IDIM + c) = __floats2half2_rn(h0, h1);
            g0 = accG[mf][nf][2]; g1 = accG[mf][nf][3];
            u0 = accU[mf][nf][2]; u1 = accU[mf][nf][3];
            h0 = u0 * (g0 / (1.0f + __expf(-g0)));
            h1 = u1 * (g1 / (1.0f + __expf(-g1)));
            *reinterpret_cast<__half2*>(hout + (size_t)(r + 8) * IDIM + c) = __floats2half2_rn(h0, h1);
        }
    }
}

// ---------------- GEMM 2: down projection ----------------
static constexpr int G2_STAGES = 4;
static constexpr int G2_KITER = IDIM / 64;           // 128
static constexpr uint32_t G2_STAGE_B = 2 * 16384;    // A + B
static constexpr uint32_t G2_SMEM = G2_STAGES * G2_STAGE_B;  // 131072

__global__ void __launch_bounds__(256, 1)
gemm2_kernel(const __half* __restrict__ A, const __half* __restrict__ B,
             float* __restrict__ out) {
    extern __shared__ char smem_raw[];
    const uint32_t sb = smem_u32(smem_raw);
    const int tid = threadIdx.x, wid = tid >> 5, lane = tid & 31;
    const int wm = wid >> 2, wn = wid & 3;

    constexpr int TILES_N = HDIM / 128;              // 16
    constexpr int GM = 8;
    int bid = blockIdx.x;
    int width = GM * TILES_N;
    int grp = bid / width, rem = bid - grp * width;
    int m0 = (grp * GM + (rem % GM)) * 128;
    int n0 = (rem / GM) * 128;

    float acc[4][4][4];
    #pragma unroll
    for (int i = 0; i < 4; i++)
        #pragma unroll
        for (int j = 0; j < 4; j++)
            #pragma unroll
            for (int e = 0; e < 4; e++) acc[i][j][e] = 0.f;

    #pragma unroll
    for (int s = 0; s < G2_STAGES - 1; s++) {
        uint32_t st = sb + s * G2_STAGE_B;
        load_block<IDIM>(st,         A, m0, s * 64, tid);
        load_block<IDIM>(st + 16384, B, n0, s * 64, tid);
        cp_commit();
    }

    for (int k = 0; k < G2_KITER; k++) {
        cp_wait<G2_STAGES - 2>();
        __syncthreads();
        int cur = k % G2_STAGES;
        int pf = k + G2_STAGES - 1;
        if (pf < G2_KITER) {
            uint32_t st = sb + (pf % G2_STAGES) * G2_STAGE_B;
            load_block<IDIM>(st,         A, m0, pf * 64, tid);
            load_block<IDIM>(st + 16384, B, n0, pf * 64, tid);
        }
        cp_commit();

        uint32_t tA = sb + cur * G2_STAGE_B;
        uint32_t tB = tA + 16384;
        #pragma unroll
        for (int kk = 0; kk < 4; kk++) {
            uint32_t a[4][4];
            #pragma unroll
            for (int mf = 0; mf < 4; mf++)
                ldsm4(a[mf][0], a[mf][1], a[mf][2], a[mf][3],
                      frag_addr(tA, wm * 64 + mf * 16, kk, lane));
            uint32_t b[4][2];
            #pragma unroll
            for (int p = 0; p < 2; p++) {
                uint32_t r0, r1, r2, r3;
                ldsm4(r0, r1, r2, r3, frag_addr(tB, wn * 32 + p * 16, kk, lane));
                b[p*2][0] = r0; b[p*2][1] = r2; b[p*2+1][0] = r1; b[p*2+1][1] = r3;
            }
            #pragma unroll
            for (int mf = 0; mf < 4; mf++)
                #pragma unroll
                for (int nf = 0; nf < 4; nf++)
                    mma16816(acc[mf][nf][0], acc[mf][nf][1], acc[mf][nf][2], acc[mf][nf][3],
                             a[mf][0], a[mf][1], a[mf][2], a[mf][3], b[nf][0], b[nf][1]);
        }
        __syncthreads();
    }

    #pragma unroll
    for (int mf = 0; mf < 4; mf++) {
        #pragma unroll
        for (int nf = 0; nf < 4; nf++) {
            int r = m0 + wm * 64 + mf * 16 + (lane >> 2);
            int c = n0 + wn * 32 + nf * 8 + ((lane & 3) << 1);
            float2 v0 = make_float2(acc[mf][nf][0], acc[mf][nf][1]);
            float2 v1 = make_float2(acc[mf][nf][2], acc[mf][nf][3]);
            *reinterpret_cast<float2*>(out + (size_t)r * HDIM + c) = v0;
            *reinterpret_cast<float2*>(out + (size_t)(r + 8) * HDIM + c) = v1;
        }
    }
}

// ---------------- host launch ----------------
extern "C" void kernel_launch(void* const* d_in, const int* in_sizes, int n_in,
                              void* d_out, int out_size) {
    const float* x  = (const float*)d_in[0];
    const float* wg = (const float*)d_in[1];
    const float* wu = (const float*)d_in[2];
    const float* wd = (const float*)d_in[3];
    float* out = (float*)d_out;
    (void)in_sizes; (void)n_in; (void)out_size;

    void *px = nullptr, *pwg = nullptr, *pwu = nullptr, *pwd = nullptr, *ph = nullptr;
    cudaGetSymbolAddress(&px,  g_x16);
    cudaGetSymbolAddress(&pwg, g_wgq);
    cudaGetSymbolAddress(&pwu, g_wuq);
    cudaGetSymbolAddress(&pwd, g_wdq);
    cudaGetSymbolAddress(&ph,  g_h16);

    cudaFuncSetAttribute(gemm1_kernel, cudaFuncAttributeMaxDynamicSharedMemorySize, (int)G1_SMEM);
    cudaFuncSetAttribute(gemm2_kernel, cudaFuncAttributeMaxDynamicSharedMemorySize, (int)G2_SMEM);

    const int NG = (IDIM * HDIM) / 128;        // 131072 groups each
    quant_kernel<<<NG / 8, 256>>>(wg, (__half*)pwg, NG);
    quant_kernel<<<NG / 8, 256>>>(wu, (__half*)pwu, NG);
    quant_kernel<<<NG / 8, 256>>>(wd, (__half*)pwd, NG);
    const int N4 = (MTOK * HDIM) / 4;          // 4194304
    cvt_kernel<<<N4 / 256, 256>>>(x, (__half*)px, N4);

    gemm1_kernel<<<(MTOK / 128) * (IDIM / 128), 256, G1_SMEM>>>(
        (const __half*)px, (const __half*)pwg, (const __half*)pwu, (__half*)ph);
    gemm2_kernel<<<(MTOK / 128) * (HDIM / 128), 256, G2_SMEM>>>(
        (const __half*)ph, (const __half*)pwd, out);
}

// round 3
// speedup vs baseline: 1.0199x; 1.0199x over previous
#include <cuda_runtime.h>
#include <cuda_fp16.h>
#include <cstdint>

// ---------------- problem dims ----------------
#define MTOK 8192   // B*S
#define HDIM 2048   // H
#define IDIM 8192   // I
// group_size G = 128 (hardcoded)

// ---------------- device scratch ----------------
__device__ __half g_x16[(size_t)MTOK * HDIM];   //  32 MB
__device__ __half g_wgq[(size_t)IDIM * HDIM];   //  32 MB
__device__ __half g_wuq[(size_t)IDIM * HDIM];   //  32 MB
__device__ __half g_wdq[(size_t)HDIM * IDIM];   //  32 MB
__device__ __half g_h16[(size_t)MTOK * IDIM];   // 128 MB

// ---------------- helpers ----------------
__device__ __forceinline__ uint32_t smem_u32(const void* p) {
    uint32_t a;
    asm("{ .reg .u64 t; cvta.to.shared.u64 t, %1; cvt.u32.u64 %0, t; }"
        : "=r"(a) : "l"(p));
    return a;
}

__device__ __forceinline__ void cp_async16(uint32_t dst, const void* src) {
    asm volatile("cp.async.cg.shared.global [%0], [%1], 16;"
                 :: "r"(dst), "l"(src) : "memory");
}
__device__ __forceinline__ void cp_commit() {
    asm volatile("cp.async.commit_group;" ::: "memory");
}
template <int N>
__device__ __forceinline__ void cp_wait() {
    asm volatile("cp.async.wait_group %0;" :: "n"(N) : "memory");
}

__device__ __forceinline__ void ldsm4(uint32_t& r0, uint32_t& r1, uint32_t& r2,
                                      uint32_t& r3, uint32_t addr) {
    asm volatile("ldmatrix.sync.aligned.m8n8.x4.shared.b16 {%0,%1,%2,%3}, [%4];"
                 : "=r"(r0), "=r"(r1), "=r"(r2), "=r"(r3) : "r"(addr));
}

__device__ __forceinline__ void mma16816(float& c0, float& c1, float& c2, float& c3,
                                         uint32_t a0, uint32_t a1, uint32_t a2, uint32_t a3,
                                         uint32_t b0, uint32_t b1) {
    asm volatile(
        "mma.sync.aligned.m16n8k16.row.col.f32.f16.f16.f32 "
        "{%0,%1,%2,%3}, {%4,%5,%6,%7}, {%8,%9}, {%0,%1,%2,%3};"
        : "+f"(c0), "+f"(c1), "+f"(c2), "+f"(c3)
        : "r"(a0), "r"(a1), "r"(a2), "r"(a3), "r"(b0), "r"(b1));
}

// ---------------- prep kernels ----------------
__global__ void __launch_bounds__(256) quant_kernel(const float* __restrict__ w,
                                                    __half* __restrict__ q, int ngroups) {
    int g = blockIdx.x * 8 + (threadIdx.x >> 5);
    if (g >= ngroups) return;
    int lane = threadIdx.x & 31;
    const float4 v = reinterpret_cast<const float4*>(w + (size_t)g * 128)[lane];
    float s = fabsf(v.x) + fabsf(v.y) + fabsf(v.z) + fabsf(v.w);
    #pragma unroll
    for (int o = 16; o; o >>= 1) s += __shfl_xor_sync(0xffffffffu, s, o);
    s *= (1.0f / 128.0f);
    float f[4] = {v.x, v.y, v.z, v.w};
    alignas(8) __half r[4];
    #pragma unroll
    for (int i = 0; i < 4; i++) {
        float sv = (f[i] > 0.f) ? s : ((f[i] < 0.f) ? -s : 0.f);
        r[i] = __float2half_rn(sv);
    }
    *reinterpret_cast<uint2*>(q + (size_t)g * 128 + lane * 4) =
        *reinterpret_cast<const uint2*>(r);
}

__global__ void __launch_bounds__(256) cvt_kernel(const float* __restrict__ x,
                                                  __half* __restrict__ y, int n4) {
    int i = blockIdx.x * 256 + threadIdx.x;
    if (i >= n4) return;
    float4 v = reinterpret_cast<const float4*>(x)[i];
    alignas(8) __half r[4] = {__float2half_rn(v.x), __float2half_rn(v.y),
                              __float2half_rn(v.z), __float2half_rn(v.w)};
    reinterpret_cast<uint2*>(y)[i] = *reinterpret_cast<const uint2*>(r);
}

// ---------------- GEMM building blocks ----------------
// SMEM tile: 128 rows x 64 halves (128B/row), 8x 16B chunks per row,
// chunk swizzle: phys = chunk ^ (row & 7).
template <int LDK>
__device__ __forceinline__ void load_block(uint32_t sdst, const __half* __restrict__ g,
                                           int row0, int k0, int tid) {
    #pragma unroll
    for (int i = 0; i < 4; i++) {
        int lin = tid + i * 256;
        int r = lin >> 3, c = lin & 7;
        const __half* src = g + (size_t)(row0 + r) * LDK + k0 + c * 8;
        uint32_t dst = sdst + r * 128 + ((c ^ (r & 7)) << 4);
        cp_async16(dst, src);
    }
}

__device__ __forceinline__ uint32_t frag_addr(uint32_t tile, int rbase, int kk, int lane) {
    int r = rbase + (lane & 15);
    int chunk = kk * 2 + (lane >> 4);
    return tile + r * 128 + ((chunk ^ (r & 7)) << 4);
}

// load 4 A fragments (64 m-rows) for k-step kk
__device__ __forceinline__ void load_afrag(uint32_t (&a)[4][4], uint32_t tile,
                                           int rbase, int kk, int lane) {
    #pragma unroll
    for (int mf = 0; mf < 4; mf++)
        ldsm4(a[mf][0], a[mf][1], a[mf][2], a[mf][3],
              frag_addr(tile, rbase + mf * 16, kk, lane));
}

// load 4 B fragments (32 n-cols) for k-step kk
__device__ __forceinline__ void load_bfrag(uint32_t (&b)[4][2], uint32_t tile,
                                           int rbase, int kk, int lane) {
    #pragma unroll
    for (int p = 0; p < 2; p++) {
        uint32_t r0, r1, r2, r3;
        ldsm4(r0, r1, r2, r3, frag_addr(tile, rbase + p * 16, kk, lane));
        b[p*2][0] = r0; b[p*2][1] = r2; b[p*2+1][0] = r1; b[p*2+1][1] = r3;
    }
}

__device__ __forceinline__ void mma_block(float (&acc)[4][4][4], const uint32_t (&a)[4][4],
                                          const uint32_t (&b)[4][2]) {
    #pragma unroll
    for (int mf = 0; mf < 4; mf++)
        #pragma unroll
        for (int nf = 0; nf < 4; nf++)
            mma16816(acc[mf][nf][0], acc[mf][nf][1], acc[mf][nf][2], acc[mf][nf][3],
                     a[mf][0], a[mf][1], a[mf][2], a[mf][3], b[nf][0], b[nf][1]);
}

// ---------------- GEMM 1: fused gate/up + SwiGLU ----------------
static constexpr int G1_STAGES = 4;
static constexpr int G1_KITER = HDIM / 64;           // 32
static constexpr uint32_t G1_STAGE_B = 3 * 16384;    // A + Bg + Bu
static constexpr uint32_t G1_SMEM = G1_STAGES * G1_STAGE_B;  // 196608

__global__ void __launch_bounds__(256, 1)
gemm1_kernel(const __half* __restrict__ A, const __half* __restrict__ Bg,
             const __half* __restrict__ Bu, __half* __restrict__ hout) {
    extern __shared__ char smem_raw[];
    const uint32_t sb = smem_u32(smem_raw);
    const int tid = threadIdx.x, wid = tid >> 5, lane = tid & 31;
    const int wm = wid >> 2, wn = wid & 3;           // warp tile 64(m) x 32(n)

    // supertile raster: groups of GM m-tiles, n varies slower
    constexpr int TILES_N = IDIM / 128;              // 64
    constexpr int GM = 16;
    int bid = blockIdx.x;
    int width = GM * TILES_N;
    int grp = bid / width, rem = bid - grp * width;
    int m0 = (grp * GM + (rem % GM)) * 128;
    int n0 = (rem / GM) * 128;

    float accG[4][4][4];
    float accU[4][4][4];
    #pragma unroll
    for (int i = 0; i < 4; i++)
        #pragma unroll
        for (int j = 0; j < 4; j++)
            #pragma unroll
            for (int e = 0; e < 4; e++) { accG[i][j][e] = 0.f; accU[i][j][e] = 0.f; }

    #pragma unroll
    for (int s = 0; s < G1_STAGES - 1; s++) {
        uint32_t st = sb + s * G1_STAGE_B;
        load_block<HDIM>(st,          A,  m0, s * 64, tid);
        load_block<HDIM>(st + 16384,  Bg, n0, s * 64, tid);
        load_block<HDIM>(st + 32768,  Bu, n0, s * 64, tid);
        cp_commit();
    }

    uint32_t a[2][4][4], bg[2][4][2], bu[2][4][2];

    for (int k = 0; k < G1_KITER; k++) {
        cp_wait<G1_STAGES - 2>();
        __syncthreads();
        // prefetch next stage
        int pf = k + G1_STAGES - 1;
        if (pf < G1_KITER) {
            uint32_t st = sb + (pf % G1_STAGES) * G1_STAGE_B;
            load_block<HDIM>(st,         A,  m0, pf * 64, tid);
            load_block<HDIM>(st + 16384, Bg, n0, pf * 64, tid);
            load_block<HDIM>(st + 32768, Bu, n0, pf * 64, tid);
        }
        cp_commit();

        uint32_t tA  = sb + (k % G1_STAGES) * G1_STAGE_B;
        uint32_t tBg = tA + 16384;
        uint32_t tBu = tA + 32768;

        // preload kk=0 fragments
        load_afrag(a[0],  tA,  wm * 64, 0, lane);
        load_bfrag(bg[0], tBg, wn * 32, 0, lane);
        load_bfrag(bu[0], tBu, wn * 32, 0, lane);

        #pragma unroll
        for (int kk = 0; kk < 4; kk++) {
            int cur = kk & 1, nxt = cur ^ 1;
            if (kk < 3) {
                load_afrag(a[nxt],  tA,  wm * 64, kk + 1, lane);
                load_bfrag(bg[nxt], tBg, wn * 32, kk + 1, lane);
                load_bfrag(bu[nxt], tBu, wn * 32, kk + 1, lane);
            }
            mma_block(accG, a[cur], bg[cur]);
            mma_block(accU, a[cur], bu[cur]);
        }
        __syncthreads();
    }

    // epilogue: h = silu(g)*u, fp16 out
    #pragma unroll
    for (int mf = 0; mf < 4; mf++) {
        #pragma unroll
        for (int nf = 0; nf < 4; nf++) {
            int r = m0 + wm * 64 + mf * 16 + (lane >> 2);
            int c = n0 + wn * 32 + nf * 8 + ((lane & 3) << 1);
            float g0 = accG[mf][nf][0], g1 = accG[mf][nf][1];
            float u0 = accU[mf][nf][0], u1 = accU[mf][nf][1];
            float h0 = u0 * (g0 / (1.0f + __expf(-g0)));
            float h1 = u1 * (g1 / (1.0f + __expf(-g1)));
            *reinterpret_cast<__half2*>(hout + (size_t)r * IDIM + c) = __floats2half2_rn(h0, h1);
            g0 = accG[mf][nf][2]; g1 = accG[mf][nf][3];
            u0 = accU[mf][nf][2]; u1 = accU[mf][nf][3];
            h0 = u0 * (g0 / (1.0f + __expf(-g0)));
            h1 = u1 * (g1 / (1.0f + __expf(-g1)));
            *reinterpret_cast<__half2*>(hout + (size_t)(r + 8) * IDIM + c) = __floats2half2_rn(h0, h1);
        }
    }
}

// ---------------- GEMM 2: down projection ----------------
static constexpr int G2_STAGES = 6;
static constexpr int G2_KITER = IDIM / 64;           // 128
static constexpr uint32_t G2_STAGE_B = 2 * 16384;    // A + B
static constexpr uint32_t G2_SMEM = G2_STAGES * G2_STAGE_B;  // 196608

__global__ void __launch_bounds__(256, 1)
gemm2_kernel(const __half* __restrict__ A, const __half* __restrict__ B,
             float* __restrict__ out) {
    extern __shared__ char smem_raw[];
    const uint32_t sb = smem_u32(smem_raw);
    const int tid = threadIdx.x, wid = tid >> 5, lane = tid & 31;
    const int wm = wid >> 2, wn = wid & 3;

    constexpr int TILES_N = HDIM / 128;              // 16
    constexpr int GM = 16;
    int bid = blockIdx.x;
    int width = GM * TILES_N;
    int grp = bid / width, rem = bid - grp * width;
    int m0 = (grp * GM + (rem % GM)) * 128;
    int n0 = (rem / GM) * 128;

    float acc[4][4][4];
    #pragma unroll
    for (int i = 0; i < 4; i++)
        #pragma unroll
        for (int j = 0; j < 4; j++)
            #pragma unroll
            for (int e = 0; e < 4; e++) acc[i][j][e] = 0.f;

    #pragma unroll
    for (int s = 0; s < G2_STAGES - 1; s++) {
        uint32_t st = sb + s * G2_STAGE_B;
        load_block<IDIM>(st,         A, m0, s * 64, tid);
        load_block<IDIM>(st + 16384, B, n0, s * 64, tid);
        cp_commit();
    }

    uint32_t a[2][4][4], b[2][4][2];

    for (int k = 0; k < G2_KITER; k++) {
        cp_wait<G2_STAGES - 2>();
        __syncthreads();
        int pf = k + G2_STAGES - 1;
        if (pf < G2_KITER) {
            uint32_t st = sb + (pf % G2_STAGES) * G2_STAGE_B;
            load_block<IDIM>(st,         A, m0, pf * 64, tid);
            load_block<IDIM>(st + 16384, B, n0, pf * 64, tid);
        }
        cp_commit();

        uint32_t tA = sb + (k % G2_STAGES) * G2_STAGE_B;
        uint32_t tB = tA + 16384;

        load_afrag(a[0], tA, wm * 64, 0, lane);
        load_bfrag(b[0], tB, wn * 32, 0, lane);

        #pragma unroll
        for (int kk = 0; kk < 4; kk++) {
            int cur = kk & 1, nxt = cur ^ 1;
            if (kk < 3) {
                load_afrag(a[nxt], tA, wm * 64, kk + 1, lane);
                load_bfrag(b[nxt], tB, wn * 32, kk + 1, lane);
            }
            mma_block(acc, a[cur], b[cur]);
        }
        __syncthreads();
    }

    #pragma unroll
    for (int mf = 0; mf < 4; mf++) {
        #pragma unroll
        for (int nf = 0; nf < 4; nf++) {
            int r = m0 + wm * 64 + mf * 16 + (lane >> 2);
            int c = n0 + wn * 32 + nf * 8 + ((lane & 3) << 1);
            float2 v0 = make_float2(acc[mf][nf][0], acc[mf][nf][1]);
            float2 v1 = make_float2(acc[mf][nf][2], acc[mf][nf][3]);
            *reinterpret_cast<float2*>(out + (size_t)r * HDIM + c) = v0;
            *reinterpret_cast<float2*>(out + (size_t)(r + 8) * HDIM + c) = v1;
        }
    }
}

// ---------------- host launch ----------------
extern "C" void kernel_launch(void* const* d_in, const int* in_sizes, int n_in,
                              void* d_out, int out_size) {
    const float* x  = (const float*)d_in[0];
    const float* wg = (const float*)d_in[1];
    const float* wu = (const float*)d_in[2];
    const float* wd = (const float*)d_in[3];
    float* out = (float*)d_out;
    (void)in_sizes; (void)n_in; (void)out_size;

    void *px = nullptr, *pwg = nullptr, *pwu = nullptr, *pwd = nullptr, *ph = nullptr;
    cudaGetSymbolAddress(&px,  g_x16);
    cudaGetSymbolAddress(&pwg, g_wgq);
    cudaGetSymbolAddress(&pwu, g_wuq);
    cudaGetSymbolAddress(&pwd, g_wdq);
    cudaGetSymbolAddress(&ph,  g_h16);

    cudaFuncSetAttribute(gemm1_kernel, cudaFuncAttributeMaxDynamicSharedMemorySize, (int)G1_SMEM);
    cudaFuncSetAttribute(gemm2_kernel, cudaFuncAttributeMaxDynamicSharedMemorySize, (int)G2_SMEM);

    const int NG = (IDIM * HDIM) / 128;        // 131072 groups each
    quant_kernel<<<NG / 8, 256>>>(wg, (__half*)pwg, NG);
    quant_kernel<<<NG / 8, 256>>>(wu, (__half*)pwu, NG);
    quant_kernel<<<NG / 8, 256>>>(wd, (__half*)pwd, NG);
    const int N4 = (MTOK * HDIM) / 4;          // 4194304
    cvt_kernel<<<N4 / 256, 256>>>(x, (__half*)px, N4);

    gemm1_kernel<<<(MTOK / 128) * (IDIM / 128), 256, G1_SMEM>>>(
        (const __half*)px, (const __half*)pwg, (const __half*)pwu, (__half*)ph);
    gemm2_kernel<<<(MTOK / 128) * (HDIM / 128), 256, G2_SMEM>>>(
        (const __half*)ph, (const __half*)pwd, out);
}